// round 12
// baseline (speedup 1.0000x reference)
#include <cuda_runtime.h>

#define NTOT 32768
#define TPB  1024
#define GAP  12          // zero guard floats between regions
#define PRE  4           // floats before region 0

// 16B-granularity bank swizzle: toggle the 16B-group bit with 128B-block parity.
// Removes the 2-way conflict of 32B-lane-stride LDS.128 (analysis loads) while
// keeping all consecutive-lane access patterns conflict-free.
__device__ __forceinline__ int sw_i(int f) { return f ^ ((f >> 3) & 4); }

__device__ __forceinline__ float4 ld4s(const float* __restrict__ sm, int f) {
    return *(const float4*)(sm + sw_i(f));
}
__device__ __forceinline__ float2 ld2s(const float* __restrict__ sm, int f) {
    return *(const float2*)(sm + sw_i(f));
}
__device__ __forceinline__ void st4s(float* __restrict__ sm, int f, float4 v) {
    *(float4*)(sm + sw_i(f)) = v;
}

// Soft-shrinkage gate, even form (u = exp(-10|y|) <= 1, no overflow):
//   gate = (u^2 E + 2u + E)/((1+uE)(u+E)),  E = exp(10b) in [1, e]
// returns y * gate.
__device__ __forceinline__ float gate_mul(float y, float E) {
    float u  = __expf(-10.0f * fabsf(y));
    float t1 = u * E;
    float num = fmaf(u, t1, fmaf(2.0f, u, E));   // u^2 E + 2u + E
    float den = (t1 + 1.0f) * (u + E);
    return __fdividef(y * num, den);
}

// Analysis level LVL: 2^LVL regions x M -> 2^(LVL+1) regions x H=M/2, in place.
// Guard zeros make the main path valid for every m0 (no edge branch).
template<int LVL>
__device__ void analysis_stage(float* __restrict__ sm,
                               const float* __restrict__ kfl,
                               const float* __restrict__ Etl) {
    const int HS = 14 - LVL;     // log2 H
    const int MS = 15 - LVL;     // log2 M
    const int H  = 1 << HS;
    const int Rout = 2 << LVL;
    const int tid = threadIdx.x;
    float4 acc[8];
#pragma unroll
    for (int j = 0; j < 8; j++) {
        int q  = tid + j * TPB;
        int e0 = q << 2;                 // output linear index, mult of 4
        int ch = e0 >> HS;
        int m0 = e0 & (H - 1);           // mult of 4
        int g  = ch >> 1;
        int bi = (g << MS) + GAP * g + PRE + (m0 << 1);   // input idx of c[2m0]
        float4 K0 = *(const float4*)(kfl + ch * 8);        // k0..k3
        float4 K1 = *(const float4*)(kfl + ch * 8 + 4);    // k4..k7
        float4 A  = ld4s(sm, bi - 4);      // c[2m0-4 .. 2m0-1]
        float4 Bv = ld4s(sm, bi);
        float4 Cv = ld4s(sm, bi + 4);
        float4 Dv = ld4s(sm, bi + 8);
        // w[u] = c[2m0-3+u];  A.y=w0 .. Dv.z=w13; y_i = sum_t K[t]*w[t+2i]
        float y0, y1, y2, y3;
        y0 =      K0.x * A.y;
        y0 = fmaf(K0.y, A.z,  y0);  y0 = fmaf(K0.z, A.w,  y0);
        y0 = fmaf(K0.w, Bv.x, y0);  y0 = fmaf(K1.x, Bv.y, y0);
        y0 = fmaf(K1.y, Bv.z, y0);  y0 = fmaf(K1.z, Bv.w, y0);
        y0 = fmaf(K1.w, Cv.x, y0);
        y1 =      K0.x * A.w;
        y1 = fmaf(K0.y, Bv.x, y1);  y1 = fmaf(K0.z, Bv.y, y1);
        y1 = fmaf(K0.w, Bv.z, y1);  y1 = fmaf(K1.x, Bv.w, y1);
        y1 = fmaf(K1.y, Cv.x, y1);  y1 = fmaf(K1.z, Cv.y, y1);
        y1 = fmaf(K1.w, Cv.z, y1);
        y2 =      K0.x * Bv.y;
        y2 = fmaf(K0.y, Bv.z, y2);  y2 = fmaf(K0.z, Bv.w, y2);
        y2 = fmaf(K0.w, Cv.x, y2);  y2 = fmaf(K1.x, Cv.y, y2);
        y2 = fmaf(K1.y, Cv.z, y2);  y2 = fmaf(K1.z, Cv.w, y2);
        y2 = fmaf(K1.w, Dv.x, y2);
        y3 =      K0.x * Bv.w;
        y3 = fmaf(K0.y, Cv.x, y3);  y3 = fmaf(K0.z, Cv.y, y3);
        y3 = fmaf(K0.w, Cv.z, y3);  y3 = fmaf(K1.x, Cv.w, y3);
        y3 = fmaf(K1.y, Dv.x, y3);  y3 = fmaf(K1.z, Dv.y, y3);
        y3 = fmaf(K1.w, Dv.z, y3);
        float E = Etl[ch];
        acc[j] = make_float4(gate_mul(y0, E), gate_mul(y1, E),
                             gate_mul(y2, E), gate_mul(y3, E));
    }
    __syncthreads();   // all reads done before in-place overwrite
#pragma unroll
    for (int j = 0; j < 8; j++) {
        int q  = tid + j * TPB;
        int e0 = q << 2;
        int ch = e0 >> HS;
        st4s(sm, e0 + GAP * ch + PRE, acc[j]);
    }
    // zero guards for the OUTPUT layout (Rout regions of H)
    if (tid < PRE) {
        sm[sw_i(tid)] = 0.0f;
    } else if (tid >= 32 && tid < 32 + GAP * Rout) {
        int u = tid - 32;
        int r = u / GAP + 1, off = u % GAP;
        sm[sw_i(r * (H + GAP) + PRE - GAP + off)] = 0.0f;
    }
    __syncthreads();
}

// Synthesis level LVL: 2^(LVL+1) regions x H -> 2^LVL regions x M=2H, in place.
// Guard zeros -> main path valid for every h0.
template<int LVL>
__device__ void synthesis_stage(float* __restrict__ sm,
                                const float* __restrict__ kfl) {
    const int MS = 15 - LVL;
    const int HS = 14 - LVL;
    const int H  = 1 << HS;
    const int M  = 1 << MS;
    const int Rout = 1 << LVL;
    const int tid = threadIdx.x;
    float4 acc[8];
#pragma unroll
    for (int j = 0; j < 8; j++) {
        int q  = tid + j * TPB;
        int e0 = q << 2;
        int g  = e0 >> MS;
        int p0 = e0 & (M - 1);           // mult of 4
        int h0 = p0 >> 1;                // mult of 2
        int ci = (g << MS) + 2 * GAP * g + PRE + h0;   // channel 2g at h0
        int di = ci + H + GAP;                          // channel 2g+1 at h0
        float4 Ka = *(const float4*)(kfl + g * 16);       // K[2g][0..3]
        float4 Kb = *(const float4*)(kfl + g * 16 + 4);   // K[2g][4..7]
        float4 Kc = *(const float4*)(kfl + g * 16 + 8);   // K[2g+1][0..3]
        float4 Kd = *(const float4*)(kfl + g * 16 + 12);  // K[2g+1][4..7]
        float2 aA = ld2s(sm, ci - 2);    // a0=c0[h0-2], a1
        float2 aB = ld2s(sm, ci);        // a2, a3
        float2 aC = ld2s(sm, ci + 2);    // a4, a5
        float2 bA = ld2s(sm, di - 2);
        float2 bB = ld2s(sm, di);
        float2 bC = ld2s(sm, di + 2);
        // even p (h'=h0+d): k1*a[d+3]+k3*a[d+2]+k5*a[d+1]+k7*a[d]  (+ channel 2g+1)
        // odd  p:           k0*a[d+4]+k2*a[d+3]+k4*a[d+2]+k6*a[d+1]
        float o0, o1, o2, o3;
        o0 =      Ka.y * aB.y;
        o0 = fmaf(Ka.w, aB.x, o0);  o0 = fmaf(Kb.y, aA.y, o0);
        o0 = fmaf(Kb.w, aA.x, o0);  o0 = fmaf(Kc.y, bB.y, o0);
        o0 = fmaf(Kc.w, bB.x, o0);  o0 = fmaf(Kd.y, bA.y, o0);
        o0 = fmaf(Kd.w, bA.x, o0);
        o1 =      Ka.x * aC.x;
        o1 = fmaf(Ka.z, aB.y, o1);  o1 = fmaf(Kb.x, aB.x, o1);
        o1 = fmaf(Kb.z, aA.y, o1);  o1 = fmaf(Kc.x, bC.x, o1);
        o1 = fmaf(Kc.z, bB.y, o1);  o1 = fmaf(Kd.x, bB.x, o1);
        o1 = fmaf(Kd.z, bA.y, o1);
        o2 =      Ka.y * aC.x;
        o2 = fmaf(Ka.w, aB.y, o2);  o2 = fmaf(Kb.y, aB.x, o2);
        o2 = fmaf(Kb.w, aA.y, o2);  o2 = fmaf(Kc.y, bC.x, o2);
        o2 = fmaf(Kc.w, bB.y, o2);  o2 = fmaf(Kd.y, bB.x, o2);
        o2 = fmaf(Kd.w, bA.y, o2);
        o3 =      Ka.x * aC.y;
        o3 = fmaf(Ka.z, aC.x, o3);  o3 = fmaf(Kb.x, aB.y, o3);
        o3 = fmaf(Kb.z, aB.x, o3);  o3 = fmaf(Kc.x, bC.y, o3);
        o3 = fmaf(Kc.z, bC.x, o3);  o3 = fmaf(Kd.x, bB.y, o3);
        o3 = fmaf(Kd.z, bB.x, o3);
        acc[j] = make_float4(o0, o1, o2, o3);
    }
    __syncthreads();
#pragma unroll
    for (int j = 0; j < 8; j++) {
        int q  = tid + j * TPB;
        int e0 = q << 2;
        int g  = e0 >> MS;
        st4s(sm, e0 + GAP * g + PRE, acc[j]);
    }
    // zero guards for the OUTPUT layout (Rout regions of M)
    if (tid < PRE) {
        sm[sw_i(tid)] = 0.0f;
    } else if (tid >= 32 && tid < 32 + GAP * Rout) {
        int u = tid - 32;
        int r = u / GAP + 1, off = u % GAP;
        sm[sw_i(r * (M + GAP) + PRE - GAP + off)] = 0.0f;
    }
    __syncthreads();
}

// Table layout: level l kernels at KOFF(l), Et at EOFF(l).
#define KOFF(l) (((1 << ((l) + 1)) * 8) - 16)
#define EOFF(l) ((1 << ((l) + 1)) - 2)
#define DATA_FLOATS (NTOT + 512)     // row data incl. guards (max 4+32*1036 = 33156)

__global__ void __launch_bounds__(TPB, 1)
wpt_kernel(const float* __restrict__ x,
           const float* __restrict__ k1, const float* __restrict__ k2,
           const float* __restrict__ k3, const float* __restrict__ k4,
           const float* __restrict__ k5,
           const float* __restrict__ b1, const float* __restrict__ b2,
           const float* __restrict__ b3, const float* __restrict__ b4,
           const float* __restrict__ b5,
           float* __restrict__ out)
{
    extern __shared__ float smem[];
    float* sm = smem;                    // guarded, swizzled row data
    float* kf = smem + DATA_FLOATS;      // 496 floats: all filter tables (unswizzled)
    float* Et = kf + 496;                // 62 floats: all exp(10b)
    const int tid = threadIdx.x;

    const float* xr   = x   + (size_t)blockIdx.x * NTOT;
    float*       orow = out + (size_t)blockIdx.x * NTOT;

    // load x into region 0 (base PRE=4)
#pragma unroll
    for (int i = tid; i < NTOT / 4; i += TPB)
        st4s(sm, PRE + 4 * i, ((const float4*)xr)[i]);
    // initial guards: [0,4) and [NTOT+4, NTOT+16)
    if (tid < PRE) sm[sw_i(tid)] = 0.0f;
    else if (tid >= 4 && tid < 16) sm[sw_i(NTOT + tid)] = 0.0f;

    // preload all tables once
    if (tid >= 512 && tid < 512 + 496) {
        int u = tid - 512;
        float v;
        if      (u < 16)  v = k1[u];
        else if (u < 48)  v = k2[u - 16];
        else if (u < 112) v = k3[u - 48];
        else if (u < 240) v = k4[u - 112];
        else              v = k5[u - 240];
        kf[u] = v;
    } else if (tid >= 256 && tid < 256 + 62) {
        int u = tid - 256;
        float bv;
        if      (u < 2)  bv = b1[u];
        else if (u < 6)  bv = b2[u - 2];
        else if (u < 14) bv = b3[u - 6];
        else if (u < 30) bv = b4[u - 14];
        else             bv = b5[u - 30];
        Et[u] = __expf(10.0f * bv);
    }
    __syncthreads();

    // ---- Analysis ----
    analysis_stage<0>(sm, kf + KOFF(0), Et + EOFF(0));
    analysis_stage<1>(sm, kf + KOFF(1), Et + EOFF(1));
    analysis_stage<2>(sm, kf + KOFF(2), Et + EOFF(2));
    analysis_stage<3>(sm, kf + KOFF(3), Et + EOFF(3));
    analysis_stage<4>(sm, kf + KOFF(4), Et + EOFF(4));

    // ---- Synthesis ----
    synthesis_stage<4>(sm, kf + KOFF(4));
    synthesis_stage<3>(sm, kf + KOFF(3));
    synthesis_stage<2>(sm, kf + KOFF(2));
    synthesis_stage<1>(sm, kf + KOFF(1));
    synthesis_stage<0>(sm, kf + KOFF(0));

#pragma unroll
    for (int i = tid; i < NTOT / 4; i += TPB)
        ((float4*)orow)[i] = ld4s(sm, PRE + 4 * i);
}

extern "C" void kernel_launch(void* const* d_in, const int* in_sizes, int n_in,
                              void* d_out, int out_size) {
    const float* x  = (const float*)d_in[0];
    const float* k1 = (const float*)d_in[1];
    const float* k2 = (const float*)d_in[2];
    const float* k3 = (const float*)d_in[3];
    const float* k4 = (const float*)d_in[4];
    const float* k5 = (const float*)d_in[5];
    const float* b1 = (const float*)d_in[6];
    const float* b2 = (const float*)d_in[7];
    const float* b3 = (const float*)d_in[8];
    const float* b4 = (const float*)d_in[9];
    const float* b5 = (const float*)d_in[10];
    float* out = (float*)d_out;

    int nrows = out_size / NTOT;   // 128
    size_t smem_bytes = (size_t)(DATA_FLOATS + 496 + 62 + 32) * sizeof(float);
    cudaFuncSetAttribute(wpt_kernel, cudaFuncAttributeMaxDynamicSharedMemorySize,
                         (int)smem_bytes);
    wpt_kernel<<<nrows, TPB, smem_bytes>>>(x, k1, k2, k3, k4, k5,
                                           b1, b2, b3, b4, b5, out);
}

// round 13
// speedup vs baseline: 1.1033x; 1.1033x over previous
#include <cuda_runtime.h>

#define NTOT 32768
#define TPB  1024
#define GAP  12          // zero guard floats between regions
#define PRE  4           // floats before region 0

// Soft-shrinkage gate, even form (u = exp(-10|y|) <= 1, no overflow):
//   gate = (u^2 E + 2u + E)/((1+uE)(u+E)),  E = exp(10b) in [1, e]
// returns y * gate.
__device__ __forceinline__ float gate_mul(float y, float E) {
    float u  = __expf(-10.0f * fabsf(y));
    float t1 = u * E;
    float num = fmaf(u, t1, fmaf(2.0f, u, E));   // u^2 E + 2u + E
    float den = (t1 + 1.0f) * (u + E);
    return __fdividef(y * num, den);
}

// Analysis level LVL: 2^LVL regions x M -> 2^(LVL+1) regions x H=M/2, in place.
// Channel-major mapping: each thread owns ONE output channel; filter taps and
// gate constant are loaded once per stage. Guard zeros remove all edge branches.
template<int LVL>
__device__ void analysis_stage(float* __restrict__ sm,
                               const float* __restrict__ kfl,
                               const float* __restrict__ Etl) {
    const int HS  = 14 - LVL;         // log2 H
    const int H   = 1 << HS;
    const int M   = H << 1;
    const int Rout = 2 << LVL;        // output channels
    const int TPC  = TPB / Rout;      // threads per channel (>= 32)
    const int tid = threadIdx.x;
    const int ch  = tid / TPC;
    const int ti  = tid - ch * TPC;
    const int g   = ch >> 1;

    const float4 K0 = *(const float4*)(kfl + ch * 8);      // k0..k3
    const float4 K1 = *(const float4*)(kfl + ch * 8 + 4);  // k4..k7
    const float  E  = Etl[ch];
    const int ibase = PRE + g * (M + GAP);                 // input region g
    const int obase = PRE + ch * (H + GAP);                // output region ch

    float4 acc[8];
#pragma unroll
    for (int k = 0; k < 8; k++) {
        int m0 = (ti + k * TPC) << 2;            // mult of 4
        int bi = ibase + (m0 << 1);              // c[2m0], mult of 4
        float4 A  = *(const float4*)(sm + bi - 4);   // c[2m0-4 .. 2m0-1]
        float4 Bv = *(const float4*)(sm + bi);
        float4 Cv = *(const float4*)(sm + bi + 4);
        float4 Dv = *(const float4*)(sm + bi + 8);
        // w[u] = c[2m0-3+u];  A.y=w0 .. Dv.z=w13; y_i = sum_t K[t]*w[t+2i]
        float y0, y1, y2, y3;
        y0 =      K0.x * A.y;
        y0 = fmaf(K0.y, A.z,  y0);  y0 = fmaf(K0.z, A.w,  y0);
        y0 = fmaf(K0.w, Bv.x, y0);  y0 = fmaf(K1.x, Bv.y, y0);
        y0 = fmaf(K1.y, Bv.z, y0);  y0 = fmaf(K1.z, Bv.w, y0);
        y0 = fmaf(K1.w, Cv.x, y0);
        y1 =      K0.x * A.w;
        y1 = fmaf(K0.y, Bv.x, y1);  y1 = fmaf(K0.z, Bv.y, y1);
        y1 = fmaf(K0.w, Bv.z, y1);  y1 = fmaf(K1.x, Bv.w, y1);
        y1 = fmaf(K1.y, Cv.x, y1);  y1 = fmaf(K1.z, Cv.y, y1);
        y1 = fmaf(K1.w, Cv.z, y1);
        y2 =      K0.x * Bv.y;
        y2 = fmaf(K0.y, Bv.z, y2);  y2 = fmaf(K0.z, Bv.w, y2);
        y2 = fmaf(K0.w, Cv.x, y2);  y2 = fmaf(K1.x, Cv.y, y2);
        y2 = fmaf(K1.y, Cv.z, y2);  y2 = fmaf(K1.z, Cv.w, y2);
        y2 = fmaf(K1.w, Dv.x, y2);
        y3 =      K0.x * Bv.w;
        y3 = fmaf(K0.y, Cv.x, y3);  y3 = fmaf(K0.z, Cv.y, y3);
        y3 = fmaf(K0.w, Cv.z, y3);  y3 = fmaf(K1.x, Cv.w, y3);
        y3 = fmaf(K1.y, Dv.x, y3);  y3 = fmaf(K1.z, Dv.y, y3);
        y3 = fmaf(K1.w, Dv.z, y3);
        acc[k] = make_float4(gate_mul(y0, E), gate_mul(y1, E),
                             gate_mul(y2, E), gate_mul(y3, E));
    }
    __syncthreads();   // all reads done before in-place overwrite
#pragma unroll
    for (int k = 0; k < 8; k++) {
        int m0 = (ti + k * TPC) << 2;
        *(float4*)(sm + obase + m0) = acc[k];
    }
    // zero guards for the OUTPUT layout (Rout regions of H)
    if (tid < PRE) {
        sm[tid] = 0.0f;
    } else if (tid >= 32 && tid < 32 + GAP * Rout) {
        int u = tid - 32;
        int r = u / GAP + 1, off = u % GAP;
        sm[r * (H + GAP) + PRE - GAP + off] = 0.0f;
    }
    __syncthreads();
}

// Synthesis level LVL: 2^(LVL+1) regions x H -> 2^LVL regions x M=2H, in place.
// Group-major mapping: each thread owns ONE output group g.
template<int LVL>
__device__ void synthesis_stage(float* __restrict__ sm,
                                const float* __restrict__ kfl) {
    const int HS = 14 - LVL;
    const int H  = 1 << HS;
    const int M  = H << 1;
    const int Rout = 1 << LVL;        // output groups
    const int TPG  = TPB / Rout;      // threads per group (>= 32)
    const int tid = threadIdx.x;
    const int g   = tid / TPG;
    const int ti  = tid - g * TPG;

    const int cbase = PRE + 2 * g * (H + GAP);   // channel 2g
    const int obase = PRE + g * (M + GAP);       // output region g
    const float* kg = kfl + g * 16;

    float4 acc[8];
#pragma unroll
    for (int k = 0; k < 8; k++) {
        int p0 = (ti + k * TPG) << 2;            // mult of 4
        int h0 = p0 >> 1;                        // mult of 2
        int ci = cbase + h0;
        int di = ci + H + GAP;                   // channel 2g+1
        // loop-invariant addresses; ptxas hoists if register pressure allows
        float4 Ka = *(const float4*)(kg);        // K[2g][0..3]
        float4 Kb = *(const float4*)(kg + 4);    // K[2g][4..7]
        float4 Kc = *(const float4*)(kg + 8);    // K[2g+1][0..3]
        float4 Kd = *(const float4*)(kg + 12);   // K[2g+1][4..7]
        float2 aA = *(const float2*)(sm + ci - 2);   // a0=c0[h0-2], a1
        float2 aB = *(const float2*)(sm + ci);       // a2, a3
        float2 aC = *(const float2*)(sm + ci + 2);   // a4, a5
        float2 bA = *(const float2*)(sm + di - 2);
        float2 bB = *(const float2*)(sm + di);
        float2 bC = *(const float2*)(sm + di + 2);
        // even p (h'=h0+d): k1*a[d+3]+k3*a[d+2]+k5*a[d+1]+k7*a[d]  (+ channel 2g+1)
        // odd  p:           k0*a[d+4]+k2*a[d+3]+k4*a[d+2]+k6*a[d+1]
        float o0, o1, o2, o3;
        o0 =      Ka.y * aB.y;
        o0 = fmaf(Ka.w, aB.x, o0);  o0 = fmaf(Kb.y, aA.y, o0);
        o0 = fmaf(Kb.w, aA.x, o0);  o0 = fmaf(Kc.y, bB.y, o0);
        o0 = fmaf(Kc.w, bB.x, o0);  o0 = fmaf(Kd.y, bA.y, o0);
        o0 = fmaf(Kd.w, bA.x, o0);
        o1 =      Ka.x * aC.x;
        o1 = fmaf(Ka.z, aB.y, o1);  o1 = fmaf(Kb.x, aB.x, o1);
        o1 = fmaf(Kb.z, aA.y, o1);  o1 = fmaf(Kc.x, bC.x, o1);
        o1 = fmaf(Kc.z, bB.y, o1);  o1 = fmaf(Kd.x, bB.x, o1);
        o1 = fmaf(Kd.z, bA.y, o1);
        o2 =      Ka.y * aC.x;
        o2 = fmaf(Ka.w, aB.y, o2);  o2 = fmaf(Kb.y, aB.x, o2);
        o2 = fmaf(Kb.w, aA.y, o2);  o2 = fmaf(Kc.y, bC.x, o2);
        o2 = fmaf(Kc.w, bB.y, o2);  o2 = fmaf(Kd.y, bB.x, o2);
        o2 = fmaf(Kd.w, bA.y, o2);
        o3 =      Ka.x * aC.y;
        o3 = fmaf(Ka.z, aC.x, o3);  o3 = fmaf(Kb.x, aB.y, o3);
        o3 = fmaf(Kb.z, aB.x, o3);  o3 = fmaf(Kc.x, bC.y, o3);
        o3 = fmaf(Kc.z, bC.x, o3);  o3 = fmaf(Kd.x, bB.y, o3);
        o3 = fmaf(Kd.z, bB.x, o3);
        acc[k] = make_float4(o0, o1, o2, o3);
    }
    __syncthreads();
#pragma unroll
    for (int k = 0; k < 8; k++) {
        int p0 = (ti + k * TPG) << 2;
        *(float4*)(sm + obase + p0) = acc[k];
    }
    // zero guards for the OUTPUT layout (Rout regions of M)
    if (tid < PRE) {
        sm[tid] = 0.0f;
    } else if (tid >= 32 && tid < 32 + GAP * Rout) {
        int u = tid - 32;
        int r = u / GAP + 1, off = u % GAP;
        sm[r * (M + GAP) + PRE - GAP + off] = 0.0f;
    }
    __syncthreads();
}

// Table layout: level l kernels at KOFF(l), Et at EOFF(l).
#define KOFF(l) (((1 << ((l) + 1)) * 8) - 16)
#define EOFF(l) ((1 << ((l) + 1)) - 2)
#define DATA_FLOATS (NTOT + 512)     // row data incl. guards (max 4+32*1036 = 33156)

__global__ void __launch_bounds__(TPB, 1)
wpt_kernel(const float* __restrict__ x,
           const float* __restrict__ k1, const float* __restrict__ k2,
           const float* __restrict__ k3, const float* __restrict__ k4,
           const float* __restrict__ k5,
           const float* __restrict__ b1, const float* __restrict__ b2,
           const float* __restrict__ b3, const float* __restrict__ b4,
           const float* __restrict__ b5,
           float* __restrict__ out)
{
    extern __shared__ float smem[];
    float* sm = smem;                    // guarded row data
    float* kf = smem + DATA_FLOATS;      // 496 floats: all filter tables
    float* Et = kf + 496;                // 62 floats: all exp(10b)
    const int tid = threadIdx.x;

    const float* xr   = x   + (size_t)blockIdx.x * NTOT;
    float*       orow = out + (size_t)blockIdx.x * NTOT;

    // load x into region 0 (base PRE=4, 16B aligned)
#pragma unroll
    for (int i = tid; i < NTOT / 4; i += TPB)
        ((float4*)(sm + PRE))[i] = ((const float4*)xr)[i];
    // initial guards: [0,4) and [NTOT+4, NTOT+16)
    if (tid < PRE) sm[tid] = 0.0f;
    else if (tid >= 4 && tid < 16) sm[NTOT + tid] = 0.0f;

    // preload all tables once
    if (tid >= 512 && tid < 512 + 496) {
        int u = tid - 512;
        float v;
        if      (u < 16)  v = k1[u];
        else if (u < 48)  v = k2[u - 16];
        else if (u < 112) v = k3[u - 48];
        else if (u < 240) v = k4[u - 112];
        else              v = k5[u - 240];
        kf[u] = v;
    } else if (tid >= 256 && tid < 256 + 62) {
        int u = tid - 256;
        float bv;
        if      (u < 2)  bv = b1[u];
        else if (u < 6)  bv = b2[u - 2];
        else if (u < 14) bv = b3[u - 6];
        else if (u < 30) bv = b4[u - 14];
        else             bv = b5[u - 30];
        Et[u] = __expf(10.0f * bv);
    }
    __syncthreads();

    // ---- Analysis ----
    analysis_stage<0>(sm, kf + KOFF(0), Et + EOFF(0));
    analysis_stage<1>(sm, kf + KOFF(1), Et + EOFF(1));
    analysis_stage<2>(sm, kf + KOFF(2), Et + EOFF(2));
    analysis_stage<3>(sm, kf + KOFF(3), Et + EOFF(3));
    analysis_stage<4>(sm, kf + KOFF(4), Et + EOFF(4));

    // ---- Synthesis ----
    synthesis_stage<4>(sm, kf + KOFF(4));
    synthesis_stage<3>(sm, kf + KOFF(3));
    synthesis_stage<2>(sm, kf + KOFF(2));
    synthesis_stage<1>(sm, kf + KOFF(1));
    synthesis_stage<0>(sm, kf + KOFF(0));

#pragma unroll
    for (int i = tid; i < NTOT / 4; i += TPB)
        ((float4*)orow)[i] = ((const float4*)(sm + PRE))[i];
}

extern "C" void kernel_launch(void* const* d_in, const int* in_sizes, int n_in,
                              void* d_out, int out_size) {
    const float* x  = (const float*)d_in[0];
    const float* k1 = (const float*)d_in[1];
    const float* k2 = (const float*)d_in[2];
    const float* k3 = (const float*)d_in[3];
    const float* k4 = (const float*)d_in[4];
    const float* k5 = (const float*)d_in[5];
    const float* b1 = (const float*)d_in[6];
    const float* b2 = (const float*)d_in[7];
    const float* b3 = (const float*)d_in[8];
    const float* b4 = (const float*)d_in[9];
    const float* b5 = (const float*)d_in[10];
    float* out = (float*)d_out;

    int nrows = out_size / NTOT;   // 128
    size_t smem_bytes = (size_t)(DATA_FLOATS + 496 + 62 + 32) * sizeof(float);
    cudaFuncSetAttribute(wpt_kernel, cudaFuncAttributeMaxDynamicSharedMemorySize,
                         (int)smem_bytes);
    wpt_kernel<<<nrows, TPB, smem_bytes>>>(x, k1, k2, k3, k4, k5,
                                           b1, b2, b3, b4, b5, out);
}

// round 14
// speedup vs baseline: 1.1116x; 1.0075x over previous
#include <cuda_runtime.h>

#define NTOT 32768
#define TPB  1024
#define GAP  12          // zero guard floats between regions
#define PRE  4           // floats before region 0

__device__ __forceinline__ float tanh_fast(float x) {
    float r;
    asm("tanh.approx.f32 %0, %1;" : "=f"(r) : "f"(x));
    return r;
}

// Soft-shrinkage gate via exact tanh identity:
//   sigmoid(10(y-b)) + sigmoid(-10(y+b)) = 1 + (tanh(5(y-b)) - tanh(5(y+b)))/2
// B = 5*b precomputed per channel. Returns y * gate. tanh.approx abs err ~1e-5.
__device__ __forceinline__ float gate_mul(float y, float B) {
    float v  = 5.0f * y;
    float d  = tanh_fast(v - B) - tanh_fast(v + B);
    return fmaf(0.5f * y, d, y);
}

// Analysis level LVL: 2^LVL regions x M -> 2^(LVL+1) regions x H=M/2, in place.
// Channel-major mapping: each thread owns ONE output channel; filter taps and
// gate constant loaded once per stage. Guard zeros remove all edge branches.
template<int LVL>
__device__ void analysis_stage(float* __restrict__ sm,
                               const float* __restrict__ kfl,
                               const float* __restrict__ Btl) {
    const int HS  = 14 - LVL;         // log2 H
    const int H   = 1 << HS;
    const int M   = H << 1;
    const int Rout = 2 << LVL;        // output channels
    const int TPC  = TPB / Rout;      // threads per channel (>= 32)
    const int tid = threadIdx.x;
    const int ch  = tid / TPC;
    const int ti  = tid - ch * TPC;
    const int g   = ch >> 1;

    const float4 K0 = *(const float4*)(kfl + ch * 8);      // k0..k3
    const float4 K1 = *(const float4*)(kfl + ch * 8 + 4);  // k4..k7
    const float  B  = Btl[ch];
    const int ibase = PRE + g * (M + GAP);                 // input region g
    const int obase = PRE + ch * (H + GAP);                // output region ch

    float4 acc[8];
#pragma unroll
    for (int k = 0; k < 8; k++) {
        int m0 = (ti + k * TPC) << 2;            // mult of 4
        int bi = ibase + (m0 << 1);              // c[2m0], mult of 4
        float4 A  = *(const float4*)(sm + bi - 4);   // c[2m0-4 .. 2m0-1]
        float4 Bv = *(const float4*)(sm + bi);
        float4 Cv = *(const float4*)(sm + bi + 4);
        float4 Dv = *(const float4*)(sm + bi + 8);
        // w[u] = c[2m0-3+u];  A.y=w0 .. Dv.z=w13; y_i = sum_t K[t]*w[t+2i]
        float y0, y1, y2, y3;
        y0 =      K0.x * A.y;
        y0 = fmaf(K0.y, A.z,  y0);  y0 = fmaf(K0.z, A.w,  y0);
        y0 = fmaf(K0.w, Bv.x, y0);  y0 = fmaf(K1.x, Bv.y, y0);
        y0 = fmaf(K1.y, Bv.z, y0);  y0 = fmaf(K1.z, Bv.w, y0);
        y0 = fmaf(K1.w, Cv.x, y0);
        y1 =      K0.x * A.w;
        y1 = fmaf(K0.y, Bv.x, y1);  y1 = fmaf(K0.z, Bv.y, y1);
        y1 = fmaf(K0.w, Bv.z, y1);  y1 = fmaf(K1.x, Bv.w, y1);
        y1 = fmaf(K1.y, Cv.x, y1);  y1 = fmaf(K1.z, Cv.y, y1);
        y1 = fmaf(K1.w, Cv.z, y1);
        y2 =      K0.x * Bv.y;
        y2 = fmaf(K0.y, Bv.z, y2);  y2 = fmaf(K0.z, Bv.w, y2);
        y2 = fmaf(K0.w, Cv.x, y2);  y2 = fmaf(K1.x, Cv.y, y2);
        y2 = fmaf(K1.y, Cv.z, y2);  y2 = fmaf(K1.z, Cv.w, y2);
        y2 = fmaf(K1.w, Dv.x, y2);
        y3 =      K0.x * Bv.w;
        y3 = fmaf(K0.y, Cv.x, y3);  y3 = fmaf(K0.z, Cv.y, y3);
        y3 = fmaf(K0.w, Cv.z, y3);  y3 = fmaf(K1.x, Cv.w, y3);
        y3 = fmaf(K1.y, Dv.x, y3);  y3 = fmaf(K1.z, Dv.y, y3);
        y3 = fmaf(K1.w, Dv.z, y3);
        acc[k] = make_float4(gate_mul(y0, B), gate_mul(y1, B),
                             gate_mul(y2, B), gate_mul(y3, B));
    }
    __syncthreads();   // all reads done before in-place overwrite
#pragma unroll
    for (int k = 0; k < 8; k++) {
        int m0 = (ti + k * TPC) << 2;
        *(float4*)(sm + obase + m0) = acc[k];
    }
    // zero guards for the OUTPUT layout (Rout regions of H)
    if (tid < PRE) {
        sm[tid] = 0.0f;
    } else if (tid >= 32 && tid < 32 + GAP * Rout) {
        int u = tid - 32;
        int r = u / GAP + 1, off = u % GAP;
        sm[r * (H + GAP) + PRE - GAP + off] = 0.0f;
    }
    __syncthreads();
}

// Synthesis level LVL: 2^(LVL+1) regions x H -> 2^LVL regions x M=2H, in place.
// Group-major mapping: each thread owns ONE output group g.
template<int LVL>
__device__ void synthesis_stage(float* __restrict__ sm,
                                const float* __restrict__ kfl) {
    const int HS = 14 - LVL;
    const int H  = 1 << HS;
    const int M  = H << 1;
    const int Rout = 1 << LVL;        // output groups
    const int TPG  = TPB / Rout;      // threads per group (>= 32)
    const int tid = threadIdx.x;
    const int g   = tid / TPG;
    const int ti  = tid - g * TPG;

    const int cbase = PRE + 2 * g * (H + GAP);   // channel 2g
    const int obase = PRE + g * (M + GAP);       // output region g
    const float* kg = kfl + g * 16;

    float4 acc[8];
#pragma unroll
    for (int k = 0; k < 8; k++) {
        int p0 = (ti + k * TPG) << 2;            // mult of 4
        int h0 = p0 >> 1;                        // mult of 2
        int ci = cbase + h0;
        int di = ci + H + GAP;                   // channel 2g+1
        float4 Ka = *(const float4*)(kg);        // K[2g][0..3]
        float4 Kb = *(const float4*)(kg + 4);    // K[2g][4..7]
        float4 Kc = *(const float4*)(kg + 8);    // K[2g+1][0..3]
        float4 Kd = *(const float4*)(kg + 12);   // K[2g+1][4..7]
        float2 aA = *(const float2*)(sm + ci - 2);   // a0=c0[h0-2], a1
        float2 aB = *(const float2*)(sm + ci);       // a2, a3
        float2 aC = *(const float2*)(sm + ci + 2);   // a4, a5
        float2 bA = *(const float2*)(sm + di - 2);
        float2 bB = *(const float2*)(sm + di);
        float2 bC = *(const float2*)(sm + di + 2);
        // even p (h'=h0+d): k1*a[d+3]+k3*a[d+2]+k5*a[d+1]+k7*a[d]  (+ channel 2g+1)
        // odd  p:           k0*a[d+4]+k2*a[d+3]+k4*a[d+2]+k6*a[d+1]
        float o0, o1, o2, o3;
        o0 =      Ka.y * aB.y;
        o0 = fmaf(Ka.w, aB.x, o0);  o0 = fmaf(Kb.y, aA.y, o0);
        o0 = fmaf(Kb.w, aA.x, o0);  o0 = fmaf(Kc.y, bB.y, o0);
        o0 = fmaf(Kc.w, bB.x, o0);  o0 = fmaf(Kd.y, bA.y, o0);
        o0 = fmaf(Kd.w, bA.x, o0);
        o1 =      Ka.x * aC.x;
        o1 = fmaf(Ka.z, aB.y, o1);  o1 = fmaf(Kb.x, aB.x, o1);
        o1 = fmaf(Kb.z, aA.y, o1);  o1 = fmaf(Kc.x, bC.x, o1);
        o1 = fmaf(Kc.z, bB.y, o1);  o1 = fmaf(Kd.x, bB.x, o1);
        o1 = fmaf(Kd.z, bA.y, o1);
        o2 =      Ka.y * aC.x;
        o2 = fmaf(Ka.w, aB.y, o2);  o2 = fmaf(Kb.y, aB.x, o2);
        o2 = fmaf(Kb.w, aA.y, o2);  o2 = fmaf(Kc.y, bC.x, o2);
        o2 = fmaf(Kc.w, bB.y, o2);  o2 = fmaf(Kd.y, bB.x, o2);
        o2 = fmaf(Kd.w, bA.y, o2);
        o3 =      Ka.x * aC.y;
        o3 = fmaf(Ka.z, aC.x, o3);  o3 = fmaf(Kb.x, aB.y, o3);
        o3 = fmaf(Kb.z, aB.x, o3);  o3 = fmaf(Kc.x, bC.y, o3);
        o3 = fmaf(Kc.z, bC.x, o3);  o3 = fmaf(Kd.x, bB.y, o3);
        o3 = fmaf(Kd.z, bB.x, o3);
        acc[k] = make_float4(o0, o1, o2, o3);
    }
    __syncthreads();
#pragma unroll
    for (int k = 0; k < 8; k++) {
        int p0 = (ti + k * TPG) << 2;
        *(float4*)(sm + obase + p0) = acc[k];
    }
    // zero guards for the OUTPUT layout (Rout regions of M)
    if (tid < PRE) {
        sm[tid] = 0.0f;
    } else if (tid >= 32 && tid < 32 + GAP * Rout) {
        int u = tid - 32;
        int r = u / GAP + 1, off = u % GAP;
        sm[r * (M + GAP) + PRE - GAP + off] = 0.0f;
    }
    __syncthreads();
}

// Table layout: level l kernels at KOFF(l), Bt at EOFF(l).
#define KOFF(l) (((1 << ((l) + 1)) * 8) - 16)
#define EOFF(l) ((1 << ((l) + 1)) - 2)
#define DATA_FLOATS (NTOT + 512)     // row data incl. guards (max 4+32*1036 = 33156)

__global__ void __launch_bounds__(TPB, 1)
wpt_kernel(const float* __restrict__ x,
           const float* __restrict__ k1, const float* __restrict__ k2,
           const float* __restrict__ k3, const float* __restrict__ k4,
           const float* __restrict__ k5,
           const float* __restrict__ b1, const float* __restrict__ b2,
           const float* __restrict__ b3, const float* __restrict__ b4,
           const float* __restrict__ b5,
           float* __restrict__ out)
{
    extern __shared__ float smem[];
    float* sm = smem;                    // guarded row data
    float* kf = smem + DATA_FLOATS;      // 496 floats: all filter tables
    float* Bt = kf + 496;                // 62 floats: all 5*b
    const int tid = threadIdx.x;

    const float* xr   = x   + (size_t)blockIdx.x * NTOT;
    float*       orow = out + (size_t)blockIdx.x * NTOT;

    // load x into region 0 (base PRE=4, 16B aligned)
#pragma unroll
    for (int i = tid; i < NTOT / 4; i += TPB)
        ((float4*)(sm + PRE))[i] = ((const float4*)xr)[i];
    // initial guards: [0,4) and [NTOT+4, NTOT+16)
    if (tid < PRE) sm[tid] = 0.0f;
    else if (tid >= 4 && tid < 16) sm[NTOT + tid] = 0.0f;

    // preload all tables once
    if (tid >= 512 && tid < 512 + 496) {
        int u = tid - 512;
        float v;
        if      (u < 16)  v = k1[u];
        else if (u < 48)  v = k2[u - 16];
        else if (u < 112) v = k3[u - 48];
        else if (u < 240) v = k4[u - 112];
        else              v = k5[u - 240];
        kf[u] = v;
    } else if (tid >= 256 && tid < 256 + 62) {
        int u = tid - 256;
        float bv;
        if      (u < 2)  bv = b1[u];
        else if (u < 6)  bv = b2[u - 2];
        else if (u < 14) bv = b3[u - 6];
        else if (u < 30) bv = b4[u - 14];
        else             bv = b5[u - 30];
        Bt[u] = 5.0f * bv;
    }
    __syncthreads();

    // ---- Analysis ----
    analysis_stage<0>(sm, kf + KOFF(0), Bt + EOFF(0));
    analysis_stage<1>(sm, kf + KOFF(1), Bt + EOFF(1));
    analysis_stage<2>(sm, kf + KOFF(2), Bt + EOFF(2));
    analysis_stage<3>(sm, kf + KOFF(3), Bt + EOFF(3));
    analysis_stage<4>(sm, kf + KOFF(4), Bt + EOFF(4));

    // ---- Synthesis ----
    synthesis_stage<4>(sm, kf + KOFF(4));
    synthesis_stage<3>(sm, kf + KOFF(3));
    synthesis_stage<2>(sm, kf + KOFF(2));
    synthesis_stage<1>(sm, kf + KOFF(1));
    synthesis_stage<0>(sm, kf + KOFF(0));

#pragma unroll
    for (int i = tid; i < NTOT / 4; i += TPB)
        ((float4*)orow)[i] = ((const float4*)(sm + PRE))[i];
}

extern "C" void kernel_launch(void* const* d_in, const int* in_sizes, int n_in,
                              void* d_out, int out_size) {
    const float* x  = (const float*)d_in[0];
    const float* k1 = (const float*)d_in[1];
    const float* k2 = (const float*)d_in[2];
    const float* k3 = (const float*)d_in[3];
    const float* k4 = (const float*)d_in[4];
    const float* k5 = (const float*)d_in[5];
    const float* b1 = (const float*)d_in[6];
    const float* b2 = (const float*)d_in[7];
    const float* b3 = (const float*)d_in[8];
    const float* b4 = (const float*)d_in[9];
    const float* b5 = (const float*)d_in[10];
    float* out = (float*)d_out;

    int nrows = out_size / NTOT;   // 128
    size_t smem_bytes = (size_t)(DATA_FLOATS + 496 + 62 + 32) * sizeof(float);
    cudaFuncSetAttribute(wpt_kernel, cudaFuncAttributeMaxDynamicSharedMemorySize,
                         (int)smem_bytes);
    wpt_kernel<<<nrows, TPB, smem_bytes>>>(x, k1, k2, k3, k4, k5,
                                           b1, b2, b3, b4, b5, out);
}

// round 17
// speedup vs baseline: 1.3514x; 1.2157x over previous
#include <cuda_runtime.h>

#define NTOT 32768
#define TPB  1024
#define GAP  12          // zero guard floats between regions
#define PRE  4           // floats before region 0

__device__ __forceinline__ float tanh_fast(float x) {
    float r;
    asm("tanh.approx.f32 %0, %1;" : "=f"(r) : "f"(x));
    return r;
}

// Soft-shrinkage gate via exact tanh identity:
//   sigmoid(10(y-b)) + sigmoid(-10(y+b)) = 1 + (tanh(5(y-b)) - tanh(5(y+b)))/2
// B = 5*b precomputed per channel. Returns y * gate. tanh.approx abs err ~1e-5.
__device__ __forceinline__ float gate_mul(float y, float B) {
    float v  = 5.0f * y;
    float d  = tanh_fast(v - B) - tanh_fast(v + B);
    return fmaf(0.5f * y, d, y);
}

// Analysis level LVL: 2^LVL regions x M -> 2^(LVL+1) regions x H=M/2, in place.
// Channel-major mapping; 2 outputs per thread-iteration so the window loads are
// lane-contiguous LDS.128 (16B lane stride -> conflict-free). Guard zeros remove
// all edge branches.
template<int LVL>
__device__ void analysis_stage(float* __restrict__ sm,
                               const float* __restrict__ kfl,
                               const float* __restrict__ Btl) {
    const int HS  = 14 - LVL;         // log2 H
    const int H   = 1 << HS;
    const int M   = H << 1;
    const int Rout = 2 << LVL;        // output channels
    const int TPC  = TPB / Rout;      // threads per channel (>= 32)
    const int tid = threadIdx.x;
    const int ch  = tid / TPC;
    const int ti  = tid - ch * TPC;
    const int g   = ch >> 1;

    const float4 K0 = *(const float4*)(kfl + ch * 8);      // k0..k3
    const float4 K1 = *(const float4*)(kfl + ch * 8 + 4);  // k4..k7
    const float  B  = Btl[ch];
    const int ibase = PRE + g * (M + GAP);                 // input region g
    const int obase = PRE + ch * (H + GAP);                // output region ch

    float2 acc[16];
#pragma unroll
    for (int k = 0; k < 16; k++) {
        int m0 = (ti + k * TPC) << 1;            // even
        int bi = ibase + (m0 << 1);              // c[2m0], mult of 4
        float4 A  = *(const float4*)(sm + bi - 4);   // c[2m0-4 .. 2m0-1]
        float4 Bv = *(const float4*)(sm + bi);       // c[2m0   .. 2m0+3]
        float4 Cv = *(const float4*)(sm + bi + 4);   // c[2m0+4 .. 2m0+7]
        // w[t] = c[2m0-3+t]; y0 = K.w[0..7], y1 = K.w[2..9]
        float y0, y1;
        y0 =      K0.x * A.y;
        y0 = fmaf(K0.y, A.z,  y0);  y0 = fmaf(K0.z, A.w,  y0);
        y0 = fmaf(K0.w, Bv.x, y0);  y0 = fmaf(K1.x, Bv.y, y0);
        y0 = fmaf(K1.y, Bv.z, y0);  y0 = fmaf(K1.z, Bv.w, y0);
        y0 = fmaf(K1.w, Cv.x, y0);
        y1 =      K0.x * A.w;
        y1 = fmaf(K0.y, Bv.x, y1);  y1 = fmaf(K0.z, Bv.y, y1);
        y1 = fmaf(K0.w, Bv.z, y1);  y1 = fmaf(K1.x, Bv.w, y1);
        y1 = fmaf(K1.y, Cv.x, y1);  y1 = fmaf(K1.z, Cv.y, y1);
        y1 = fmaf(K1.w, Cv.z, y1);
        acc[k] = make_float2(gate_mul(y0, B), gate_mul(y1, B));
    }
    __syncthreads();   // all reads done before in-place overwrite
#pragma unroll
    for (int k = 0; k < 16; k++) {
        int m0 = (ti + k * TPC) << 1;
        *(float2*)(sm + obase + m0) = acc[k];
    }
    // zero guards for the OUTPUT layout (Rout regions of H)
    if (tid < PRE) {
        sm[tid] = 0.0f;
    } else if (tid >= 32 && tid < 32 + GAP * Rout) {
        int u = tid - 32;
        int r = u / GAP + 1, off = u % GAP;
        sm[r * (H + GAP) + PRE - GAP + off] = 0.0f;
    }
    __syncthreads();
}

// Synthesis level LVL: 2^(LVL+1) regions x H -> 2^LVL regions x M=2H, in place.
// Group-major mapping: each thread owns ONE output group g.
template<int LVL>
__device__ void synthesis_stage(float* __restrict__ sm,
                                const float* __restrict__ kfl) {
    const int HS = 14 - LVL;
    const int H  = 1 << HS;
    const int M  = H << 1;
    const int Rout = 1 << LVL;        // output groups
    const int TPG  = TPB / Rout;      // threads per group (>= 32)
    const int tid = threadIdx.x;
    const int g   = tid / TPG;
    const int ti  = tid - g * TPG;

    const int cbase = PRE + 2 * g * (H + GAP);   // channel 2g
    const int obase = PRE + g * (M + GAP);       // output region g
    const float* kg = kfl + g * 16;

    float4 acc[8];
#pragma unroll
    for (int k = 0; k < 8; k++) {
        int p0 = (ti + k * TPG) << 2;            // mult of 4
        int h0 = p0 >> 1;                        // mult of 2
        int ci = cbase + h0;
        int di = ci + H + GAP;                   // channel 2g+1
        float4 Ka = *(const float4*)(kg);        // K[2g][0..3]
        float4 Kb = *(const float4*)(kg + 4);    // K[2g][4..7]
        float4 Kc = *(const float4*)(kg + 8);    // K[2g+1][0..3]
        float4 Kd = *(const float4*)(kg + 12);   // K[2g+1][4..7]
        float2 aA = *(const float2*)(sm + ci - 2);   // a0=c0[h0-2], a1
        float2 aB = *(const float2*)(sm + ci);       // a2, a3
        float2 aC = *(const float2*)(sm + ci + 2);   // a4, a5
        float2 bA = *(const float2*)(sm + di - 2);
        float2 bB = *(const float2*)(sm + di);
        float2 bC = *(const float2*)(sm + di + 2);
        // even p (h'=h0+d): k1*a[d+3]+k3*a[d+2]+k5*a[d+1]+k7*a[d]  (+ channel 2g+1)
        // odd  p:           k0*a[d+4]+k2*a[d+3]+k4*a[d+2]+k6*a[d+1]
        float o0, o1, o2, o3;
        o0 =      Ka.y * aB.y;
        o0 = fmaf(Ka.w, aB.x, o0);  o0 = fmaf(Kb.y, aA.y, o0);
        o0 = fmaf(Kb.w, aA.x, o0);  o0 = fmaf(Kc.y, bB.y, o0);
        o0 = fmaf(Kc.w, bB.x, o0);  o0 = fmaf(Kd.y, bA.y, o0);
        o0 = fmaf(Kd.w, bA.x, o0);
        o1 =      Ka.x * aC.x;
        o1 = fmaf(Ka.z, aB.y, o1);  o1 = fmaf(Kb.x, aB.x, o1);
        o1 = fmaf(Kb.z, aA.y, o1);  o1 = fmaf(Kc.x, bC.x, o1);
        o1 = fmaf(Kc.z, bB.y, o1);  o1 = fmaf(Kd.x, bB.x, o1);
        o1 = fmaf(Kd.z, bA.y, o1);
        o2 =      Ka.y * aC.x;
        o2 = fmaf(Ka.w, aB.y, o2);  o2 = fmaf(Kb.y, aB.x, o2);
        o2 = fmaf(Kb.w, aA.y, o2);  o2 = fmaf(Kc.y, bC.x, o2);
        o2 = fmaf(Kc.w, bB.y, o2);  o2 = fmaf(Kd.y, bB.x, o2);
        o2 = fmaf(Kd.w, bA.y, o2);
        o3 =      Ka.x * aC.y;
        o3 = fmaf(Ka.z, aC.x, o3);  o3 = fmaf(Kb.x, aB.y, o3);
        o3 = fmaf(Kb.z, aB.x, o3);  o3 = fmaf(Kc.x, bC.y, o3);
        o3 = fmaf(Kc.z, bC.x, o3);  o3 = fmaf(Kd.x, bB.y, o3);
        o3 = fmaf(Kd.z, bB.x, o3);
        acc[k] = make_float4(o0, o1, o2, o3);
    }
    __syncthreads();
#pragma unroll
    for (int k = 0; k < 8; k++) {
        int p0 = (ti + k * TPG) << 2;
        *(float4*)(sm + obase + p0) = acc[k];
    }
    // zero guards for the OUTPUT layout (Rout regions of M)
    if (tid < PRE) {
        sm[tid] = 0.0f;
    } else if (tid >= 32 && tid < 32 + GAP * Rout) {
        int u = tid - 32;
        int r = u / GAP + 1, off = u % GAP;
        sm[r * (M + GAP) + PRE - GAP + off] = 0.0f;
    }
    __syncthreads();
}

// Table layout: level l kernels at KOFF(l), Bt at EOFF(l).
#define KOFF(l) (((1 << ((l) + 1)) * 8) - 16)
#define EOFF(l) ((1 << ((l) + 1)) - 2)
#define DATA_FLOATS (NTOT + 512)     // row data incl. guards (max 4+32*1036 = 33156)

__global__ void __launch_bounds__(TPB, 1)
wpt_kernel(const float* __restrict__ x,
           const float* __restrict__ k1, const float* __restrict__ k2,
           const float* __restrict__ k3, const float* __restrict__ k4,
           const float* __restrict__ k5,
           const float* __restrict__ b1, const float* __restrict__ b2,
           const float* __restrict__ b3, const float* __restrict__ b4,
           const float* __restrict__ b5,
           float* __restrict__ out)
{
    extern __shared__ float smem[];
    float* sm = smem;                    // guarded row data
    float* kf = smem + DATA_FLOATS;      // 496 floats: all filter tables
    float* Bt = kf + 496;                // 62 floats: all 5*b
    const int tid = threadIdx.x;

    const float* xr   = x   + (size_t)blockIdx.x * NTOT;
    float*       orow = out + (size_t)blockIdx.x * NTOT;

    // load x into region 0 (base PRE=4, 16B aligned)
#pragma unroll
    for (int i = tid; i < NTOT / 4; i += TPB)
        ((float4*)(sm + PRE))[i] = ((const float4*)xr)[i];
    // initial guards: [0,4) and [NTOT+4, NTOT+16)
    if (tid < PRE) sm[tid] = 0.0f;
    else if (tid >= 4 && tid < 16) sm[NTOT + tid] = 0.0f;

    // preload all tables once
    if (tid >= 512 && tid < 512 + 496) {
        int u = tid - 512;
        float v;
        if      (u < 16)  v = k1[u];
        else if (u < 48)  v = k2[u - 16];
        else if (u < 112) v = k3[u - 48];
        else if (u < 240) v = k4[u - 112];
        else              v = k5[u - 240];
        kf[u] = v;
    } else if (tid >= 256 && tid < 256 + 62) {
        int u = tid - 256;
        float bv;
        if      (u < 2)  bv = b1[u];
        else if (u < 6)  bv = b2[u - 2];
        else if (u < 14) bv = b3[u - 6];
        else if (u < 30) bv = b4[u - 14];
        else             bv = b5[u - 30];
        Bt[u] = 5.0f * bv;
    }
    __syncthreads();

    // ---- Analysis ----
    analysis_stage<0>(sm, kf + KOFF(0), Bt + EOFF(0));
    analysis_stage<1>(sm, kf + KOFF(1), Bt + EOFF(1));
    analysis_stage<2>(sm, kf + KOFF(2), Bt + EOFF(2));
    analysis_stage<3>(sm, kf + KOFF(3), Bt + EOFF(3));
    analysis_stage<4>(sm, kf + KOFF(4), Bt + EOFF(4));

    // ---- Synthesis ----
    synthesis_stage<4>(sm, kf + KOFF(4));
    synthesis_stage<3>(sm, kf + KOFF(3));
    synthesis_stage<2>(sm, kf + KOFF(2));
    synthesis_stage<1>(sm, kf + KOFF(1));
    synthesis_stage<0>(sm, kf + KOFF(0));

#pragma unroll
    for (int i = tid; i < NTOT / 4; i += TPB)
        ((float4*)orow)[i] = ((const float4*)(sm + PRE))[i];
}

extern "C" void kernel_launch(void* const* d_in, const int* in_sizes, int n_in,
                              void* d_out, int out_size) {
    const float* x  = (const float*)d_in[0];
    const float* k1 = (const float*)d_in[1];
    const float* k2 = (const float*)d_in[2];
    const float* k3 = (const float*)d_in[3];
    const float* k4 = (const float*)d_in[4];
    const float* k5 = (const float*)d_in[5];
    const float* b1 = (const float*)d_in[6];
    const float* b2 = (const float*)d_in[7];
    const float* b3 = (const float*)d_in[8];
    const float* b4 = (const float*)d_in[9];
    const float* b5 = (const float*)d_in[10];
    float* out = (float*)d_out;

    int nrows = out_size / NTOT;   // 128
    size_t smem_bytes = (size_t)(DATA_FLOATS + 496 + 62 + 32) * sizeof(float);
    cudaFuncSetAttribute(wpt_kernel, cudaFuncAttributeMaxDynamicSharedMemorySize,
                         (int)smem_bytes);
    wpt_kernel<<<nrows, TPB, smem_bytes>>>(x, k1, k2, k3, k4, k5,
                                           b1, b2, b3, b4, b5, out);
}